// round 2
// baseline (speedup 1.0000x reference)
#include <cuda_runtime.h>
#include <math.h>

#define NB 512
#define NL 128
#define ND 256
#define NF 512
#define NE 8

// Scratch (allocation-free rule: __device__ globals)
__device__ float g_gates[NB * NE];                 // normalized gates [b][e]
__device__ float g_H[(size_t)NB * NL * NF];        // 128 MB intermediate H

// ---------------------------------------------------------------------------
// Gate kernel: softmax over E=8, mask, renormalize with +1e-9
// ---------------------------------------------------------------------------
__global__ void gate_kernel(const float* __restrict__ logits,
                            const int* __restrict__ masks) {
    int b = blockIdx.x * blockDim.x + threadIdx.x;
    if (b >= NB) return;
    float v[NE];
    float mx = -1e30f;
#pragma unroll
    for (int e = 0; e < NE; e++) { v[e] = logits[b * NE + e]; mx = fmaxf(mx, v[e]); }
    float s = 0.f;
#pragma unroll
    for (int e = 0; e < NE; e++) { v[e] = expf(v[e] - mx); s += v[e]; }
    float inv = 1.f / s;
    float gs = 0.f;
#pragma unroll
    for (int e = 0; e < NE; e++) {
        v[e] = (masks[b * NE + e] == 1) ? v[e] * inv : 0.f;
        gs += v[e];
    }
    float d = 1.f / (gs + 1e-9f);
#pragma unroll
    for (int e = 0; e < NE; e++) g_gates[b * NE + e] = v[e] * d;
}

// ---------------------------------------------------------------------------
// GEMM1: H = gelu(X @ W1[e] + b1[e]) for rows whose gate[b][e] > 0
// X: [NB*NL, ND] row-major, W1[e]: [ND, NF] row-major, H: [NB*NL, NF]
// Tile: 64x64, BK=32, 256 threads, 4x4 per thread.
// ---------------------------------------------------------------------------
__global__ void gemm1_kernel(const float* __restrict__ X,
                             const float* __restrict__ W1,
                             const float* __restrict__ b1,
                             int e) {
    const int m0 = blockIdx.x * 64;
    const int n0 = blockIdx.y * 64;
    const int b  = m0 >> 7;  // / NL (=128); 64-row tiles never cross a sample
    const float gate = g_gates[b * NE + e];
    if (gate == 0.0f) return;

    __shared__ float As[32][65];   // k-major (transposed), +1 pad
    __shared__ float Bs[32][64];

    const int tid = threadIdx.x;
    const int tx = tid & 15;
    const int ty = tid >> 4;

    const float* Ag = X + (size_t)m0 * ND;
    const float* Bg = W1 + (size_t)e * ND * NF + n0;

    float acc[4][4] = {};

    for (int k0 = 0; k0 < ND; k0 += 32) {
        // Load A tile: 64 rows x 32 cols (transpose into As[k][m])
#pragma unroll
        for (int i = 0; i < 2; i++) {
            int q   = tid + i * 256;     // 0..511 float4 slots
            int row = q >> 3;            // 8 float4 per row
            int kc  = (q & 7) << 2;
            float4 v = *(const float4*)(Ag + (size_t)row * ND + k0 + kc);
            As[kc + 0][row] = v.x; As[kc + 1][row] = v.y;
            As[kc + 2][row] = v.z; As[kc + 3][row] = v.w;
        }
        // Load B tile: 32 rows x 64 cols
#pragma unroll
        for (int i = 0; i < 2; i++) {
            int q   = tid + i * 256;
            int row = q >> 4;            // 16 float4 per row
            int c   = (q & 15) << 2;
            *(float4*)&Bs[row][c] = *(const float4*)(Bg + (size_t)(k0 + row) * NF + c);
        }
        __syncthreads();
#pragma unroll
        for (int k = 0; k < 32; k++) {
            float4 bv = *(float4*)&Bs[k][tx * 4];
            float ar[4];
#pragma unroll
            for (int i = 0; i < 4; i++) ar[i] = As[k][ty * 4 + i];
#pragma unroll
            for (int i = 0; i < 4; i++) {
                acc[i][0] += ar[i] * bv.x;
                acc[i][1] += ar[i] * bv.y;
                acc[i][2] += ar[i] * bv.z;
                acc[i][3] += ar[i] * bv.w;
            }
        }
        __syncthreads();
    }

    // Epilogue: bias + exact GELU, write H (vectorized)
    const float* bias = b1 + e * NF + n0;
    float* Hp = g_H + (size_t)m0 * NF + n0;
#pragma unroll
    for (int i = 0; i < 4; i++) {
        int r = ty * 4 + i;
        int c = tx * 4;
        float4 o;
        float v0 = acc[i][0] + bias[c + 0];
        float v1 = acc[i][1] + bias[c + 1];
        float v2 = acc[i][2] + bias[c + 2];
        float v3 = acc[i][3] + bias[c + 3];
        o.x = 0.5f * v0 * (1.0f + erff(v0 * 0.70710678118654752f));
        o.y = 0.5f * v1 * (1.0f + erff(v1 * 0.70710678118654752f));
        o.z = 0.5f * v2 * (1.0f + erff(v2 * 0.70710678118654752f));
        o.w = 0.5f * v3 * (1.0f + erff(v3 * 0.70710678118654752f));
        *(float4*)(Hp + (size_t)r * NF + c) = o;
    }
}

// ---------------------------------------------------------------------------
// GEMM2: out += gate * (H @ W2[e] + b2[e]) for active rows
// H: [NB*NL, NF], W2[e]: [NF, ND], out: [NB*NL, ND]
// Experts launched sequentially -> plain read-modify-write, no atomics.
// ---------------------------------------------------------------------------
__global__ void gemm2_kernel(const float* __restrict__ W2,
                             const float* __restrict__ b2,
                             float* __restrict__ out,
                             int e) {
    const int m0 = blockIdx.x * 64;
    const int n0 = blockIdx.y * 64;
    const int b  = m0 >> 7;
    const float gate = g_gates[b * NE + e];
    if (gate == 0.0f) return;

    __shared__ float As[32][65];
    __shared__ float Bs[32][64];

    const int tid = threadIdx.x;
    const int tx = tid & 15;
    const int ty = tid >> 4;

    const float* Ag = g_H + (size_t)m0 * NF;
    const float* Bg = W2 + (size_t)e * NF * ND + n0;

    float acc[4][4] = {};

    for (int k0 = 0; k0 < NF; k0 += 32) {
#pragma unroll
        for (int i = 0; i < 2; i++) {
            int q   = tid + i * 256;
            int row = q >> 3;
            int kc  = (q & 7) << 2;
            float4 v = *(const float4*)(Ag + (size_t)row * NF + k0 + kc);
            As[kc + 0][row] = v.x; As[kc + 1][row] = v.y;
            As[kc + 2][row] = v.z; As[kc + 3][row] = v.w;
        }
#pragma unroll
        for (int i = 0; i < 2; i++) {
            int q   = tid + i * 256;
            int row = q >> 4;
            int c   = (q & 15) << 2;
            *(float4*)&Bs[row][c] = *(const float4*)(Bg + (size_t)(k0 + row) * ND + c);
        }
        __syncthreads();
#pragma unroll
        for (int k = 0; k < 32; k++) {
            float4 bv = *(float4*)&Bs[k][tx * 4];
            float ar[4];
#pragma unroll
            for (int i = 0; i < 4; i++) ar[i] = As[k][ty * 4 + i];
#pragma unroll
            for (int i = 0; i < 4; i++) {
                acc[i][0] += ar[i] * bv.x;
                acc[i][1] += ar[i] * bv.y;
                acc[i][2] += ar[i] * bv.z;
                acc[i][3] += ar[i] * bv.w;
            }
        }
        __syncthreads();
    }

    const float* bias = b2 + e * ND + n0;
    float* Op = out + (size_t)m0 * ND + n0;
#pragma unroll
    for (int i = 0; i < 4; i++) {
        int r = ty * 4 + i;
        int c = tx * 4;
        float4 cur = *(float4*)(Op + (size_t)r * ND + c);
        cur.x += gate * (acc[i][0] + bias[c + 0]);
        cur.y += gate * (acc[i][1] + bias[c + 1]);
        cur.z += gate * (acc[i][2] + bias[c + 2]);
        cur.w += gate * (acc[i][3] + bias[c + 3]);
        *(float4*)(Op + (size_t)r * ND + c) = cur;
    }
}

// ---------------------------------------------------------------------------
extern "C" void kernel_launch(void* const* d_in, const int* in_sizes, int n_in,
                              void* d_out, int out_size) {
    const float* x      = (const float*)d_in[0];   // [512,128,256]
    const float* logits = (const float*)d_in[1];   // [512,8]
    const float* W1     = (const float*)d_in[2];   // [8,256,512]
    const float* b1     = (const float*)d_in[3];   // [8,512]
    const float* W2     = (const float*)d_in[4];   // [8,512,256]
    const float* b2     = (const float*)d_in[5];   // [8,256]
    const int*   masks  = (const int*)d_in[6];     // [512,8]
    float* out = (float*)d_out;

    cudaMemsetAsync(out, 0, (size_t)out_size * sizeof(float), 0);
    gate_kernel<<<2, 256>>>(logits, masks);

    for (int e = 0; e < NE; e++) {
        gemm1_kernel<<<dim3((NB * NL) / 64, NF / 64), 256>>>(x, W1, b1, e);
        gemm2_kernel<<<dim3((NB * NL) / 64, ND / 64), 256>>>(W2, b2, out, e);
    }
}

// round 4
// speedup vs baseline: 2.2063x; 2.2063x over previous
#include <cuda_runtime.h>
#include <cuda_bf16.h>
#include <math.h>
#include <stdint.h>

#define NB 512
#define NL 128
#define ND 256
#define NF 512
#define NE 8

// ---------------------------------------------------------------------------
// Device scratch (allocation-free rule)
// ---------------------------------------------------------------------------
__device__ float g_gates[NB * NE];
__device__ __nv_bfloat16 g_Xhi[(size_t)NB * NL * ND];
__device__ __nv_bfloat16 g_Xlo[(size_t)NB * NL * ND];
__device__ __nv_bfloat16 g_W1Thi[(size_t)NE * NF * ND];   // [e][n][k]
__device__ __nv_bfloat16 g_W1Tlo[(size_t)NE * NF * ND];
__device__ __nv_bfloat16 g_W2Thi[(size_t)NE * ND * NF];   // [e][n][k]
__device__ __nv_bfloat16 g_W2Tlo[(size_t)NE * ND * NF];
__device__ __nv_bfloat16 g_Hhi[(size_t)NB * NE * NL * NF];  // 536 MB
__device__ __nv_bfloat16 g_Hlo[(size_t)NB * NE * NL * NF];  // 536 MB

// ---------------------------------------------------------------------------
// PTX helpers — baseline (non-'a') features only: cp.async, ldmatrix, mma.sync
// ---------------------------------------------------------------------------
__device__ __forceinline__ uint32_t smem_u32(const void* p) {
    uint32_t a;
    asm("{ .reg .u64 t; cvta.to.shared.u64 t, %1; cvt.u32.u64 %0, t; }" : "=r"(a) : "l"(p));
    return a;
}
__device__ __forceinline__ void cp16(uint32_t dst, const void* src) {
    asm volatile("cp.async.cg.shared.global [%0], [%1], 16;" :: "r"(dst), "l"(src));
}
#define CP_COMMIT() asm volatile("cp.async.commit_group;" ::: "memory")
#define CP_WAIT0()  asm volatile("cp.async.wait_group 0;" ::: "memory")

#define LDSM4(r0, r1, r2, r3, addr) \
    asm volatile("ldmatrix.sync.aligned.m8n8.x4.shared.b16 {%0,%1,%2,%3}, [%4];" \
                 : "=r"(r0), "=r"(r1), "=r"(r2), "=r"(r3) : "r"(addr))

#define MMA16816(c, a, b0, b1) \
    asm volatile("mma.sync.aligned.m16n8k16.row.col.f32.bf16.bf16.f32 " \
                 "{%0,%1,%2,%3}, {%4,%5,%6,%7}, {%8,%9}, {%0,%1,%2,%3};" \
                 : "+f"((c)[0]), "+f"((c)[1]), "+f"((c)[2]), "+f"((c)[3]) \
                 : "r"((a)[0]), "r"((a)[1]), "r"((a)[2]), "r"((a)[3]), \
                   "r"(b0), "r"(b1))

__device__ __forceinline__ float gelu_exact(float v) {
    return 0.5f * v * (1.0f + erff(v * 0.70710678118654752f));
}

// SMEM geometry: tiles are [128 rows][32 cols] bf16, padded to stride 40 elems
// (80 B = 20 banks -> ldmatrix 8-row phases land on disjoint bank quads).
#define TILE_BYTES (128 * 40 * 2)          // 10240
#define SM_A(st) ((st) * TILE_BYTES)
#define SM_B(st) (2 * TILE_BYTES + (st) * TILE_BYTES)
#define SM_TOTAL (4 * TILE_BYTES)          // 40960

// Fill one 128x32 tile pair (A and B) for a stage via cp.async (4 x 16B/thread).
__device__ __forceinline__ void fill_stage(uint32_t smb, int st,
                                           const __nv_bfloat16* As, int Astride,
                                           const __nv_bfloat16* Bs, int Bstride,
                                           int tid) {
#pragma unroll
    for (int i = 0; i < 2; i++) {
        int q = tid + i * 256;
        int r = q >> 2;
        int c = (q & 3) << 3;
        cp16(smb + SM_A(st) + r * 80 + c * 2, As + (size_t)r * Astride + c);
        cp16(smb + SM_B(st) + r * 80 + c * 2, Bs + (size_t)r * Bstride + c);
    }
    CP_COMMIT();
}

// One BK=32 compute step: 8 ldmatrix.x4 (A) + 4 ldmatrix.x4 (B) + 32 HMMA.
__device__ __forceinline__ void compute_stage(uint32_t smb, int st, int wm, int wn,
                                              int lane, float acc[4][4][4]) {
#pragma unroll
    for (int ks = 0; ks < 2; ks++) {
        uint32_t a[4][4];
#pragma unroll
        for (int mi = 0; mi < 4; mi++) {
            uint32_t ad = smb + SM_A(st) +
                ((wm * 64 + mi * 16 + (lane & 15)) * 40 + ks * 16 + (lane >> 4) * 8) * 2;
            LDSM4(a[mi][0], a[mi][1], a[mi][2], a[mi][3], ad);
        }
        uint32_t bfr[2][4];
        int quad = lane >> 3;
#pragma unroll
        for (int g = 0; g < 2; g++) {
            uint32_t bd = smb + SM_B(st) +
                ((wn * 32 + g * 16 + (quad >> 1) * 8 + (lane & 7)) * 40 +
                 ks * 16 + (quad & 1) * 8) * 2;
            LDSM4(bfr[g][0], bfr[g][1], bfr[g][2], bfr[g][3], bd);
        }
#pragma unroll
        for (int mi = 0; mi < 4; mi++)
#pragma unroll
            for (int ni = 0; ni < 4; ni++)
                MMA16816(acc[mi][ni], a[mi],
                         bfr[ni >> 1][(ni & 1) * 2], bfr[ni >> 1][(ni & 1) * 2 + 1]);
    }
}

// ---------------------------------------------------------------------------
// Prep kernels
// ---------------------------------------------------------------------------
__global__ void gate_kernel(const float* __restrict__ logits, const int* __restrict__ masks) {
    int b = blockIdx.x * blockDim.x + threadIdx.x;
    if (b >= NB) return;
    float v[NE]; float mx = -1e30f;
#pragma unroll
    for (int e = 0; e < NE; e++) { v[e] = logits[b * NE + e]; mx = fmaxf(mx, v[e]); }
    float s = 0.f;
#pragma unroll
    for (int e = 0; e < NE; e++) { v[e] = expf(v[e] - mx); s += v[e]; }
    float inv = 1.f / s; float gs = 0.f;
#pragma unroll
    for (int e = 0; e < NE; e++) { v[e] = (masks[b * NE + e] == 1) ? v[e] * inv : 0.f; gs += v[e]; }
    float d = 1.f / (gs + 1e-9f);
#pragma unroll
    for (int e = 0; e < NE; e++) g_gates[b * NE + e] = v[e] * d;
}

__global__ void prep_x(const float* __restrict__ x) {
    size_t n = (size_t)NB * NL * ND;
    for (size_t i = blockIdx.x * (size_t)blockDim.x + threadIdx.x; i < n;
         i += (size_t)gridDim.x * blockDim.x) {
        float v = x[i];
        __nv_bfloat16 hi = __float2bfloat16(v);
        g_Xhi[i] = hi;
        g_Xlo[i] = __float2bfloat16(v - __bfloat162float(hi));
    }
}
__global__ void prep_w1(const float* __restrict__ W1) {
    int n = NE * NF * ND;
    for (int i = blockIdx.x * blockDim.x + threadIdx.x; i < n; i += gridDim.x * blockDim.x) {
        int e = i / (NF * ND), r = i % (NF * ND);
        int nn = r / ND, k = r % ND;
        float v = W1[(size_t)e * ND * NF + (size_t)k * NF + nn];
        __nv_bfloat16 hi = __float2bfloat16(v);
        g_W1Thi[i] = hi;
        g_W1Tlo[i] = __float2bfloat16(v - __bfloat162float(hi));
    }
}
__global__ void prep_w2(const float* __restrict__ W2) {
    int n = NE * ND * NF;
    for (int i = blockIdx.x * blockDim.x + threadIdx.x; i < n; i += gridDim.x * blockDim.x) {
        int e = i / (ND * NF), r = i % (ND * NF);
        int nn = r / NF, k = r % NF;
        float v = W2[(size_t)e * NF * ND + (size_t)k * ND + nn];
        __nv_bfloat16 hi = __float2bfloat16(v);
        g_W2Thi[i] = hi;
        g_W2Tlo[i] = __float2bfloat16(v - __bfloat162float(hi));
    }
}

// ---------------------------------------------------------------------------
// GEMM1: per active (b, ntile, e): D = X'[128, 768] @ W1'[768, 128]
// K' segments of 256: {Ahi*Bhi, Alo*Bhi, Ahi*Blo}. Epilogue: gate*gelu(D+b1)
// split to bf16 hi/lo -> H scratch.
// ---------------------------------------------------------------------------
__global__ void __launch_bounds__(256, 2) gemm1_kernel(const float* __restrict__ b1) {
    const int b = blockIdx.x, nt = blockIdx.y, e = blockIdx.z;
    const float gate = g_gates[b * NE + e];
    if (gate == 0.0f) return;

    __shared__ __align__(128) char sm[SM_TOTAL];
    const uint32_t smb = smem_u32(sm);
    const int tid = threadIdx.x, lane = tid & 31, wid = tid >> 5;
    const int wm = wid & 1, wn = wid >> 1;

    const __nv_bfloat16* Ah = g_Xhi + (size_t)b * NL * ND;
    const __nv_bfloat16* Al = g_Xlo + (size_t)b * NL * ND;
    const __nv_bfloat16* Bh = g_W1Thi + ((size_t)e * NF + nt * 128) * ND;
    const __nv_bfloat16* Bl = g_W1Tlo + ((size_t)e * NF + nt * 128) * ND;
    const __nv_bfloat16* Aseg[3] = {Ah, Al, Ah};
    const __nv_bfloat16* Bseg[3] = {Bh, Bh, Bl};

    float acc[4][4][4] = {};

    // chunk kc in [0,24): seg = kc/8, k = (kc%8)*32
    {
        fill_stage(smb, 0, Aseg[0], ND, Bseg[0], ND, tid);
    }
    for (int kc = 0; kc < 24; kc++) {
        CP_WAIT0();
        __syncthreads();
        if (kc < 23) {
            int kn = kc + 1;
            int seg = kn >> 3, k = (kn & 7) << 5;
            fill_stage(smb, kn & 1, Aseg[seg] + k, ND, Bseg[seg] + k, ND, tid);
        }
        compute_stage(smb, kc & 1, wm, wn, lane, acc);
        __syncthreads();
    }

    // Epilogue
    const int r0 = lane >> 2, c0 = (lane & 3) * 2;
    __nv_bfloat16* Hh = g_Hhi + (size_t)(b * NE + e) * NL * NF;
    __nv_bfloat16* Hl = g_Hlo + (size_t)(b * NE + e) * NL * NF;
#pragma unroll
    for (int mi = 0; mi < 4; mi++) {
#pragma unroll
        for (int ni = 0; ni < 4; ni++) {
            int col = nt * 128 + wn * 32 + ni * 8 + c0;
            float bb0 = __ldg(b1 + e * NF + col);
            float bb1 = __ldg(b1 + e * NF + col + 1);
#pragma unroll
            for (int h = 0; h < 2; h++) {
                int row = wm * 64 + mi * 16 + r0 + h * 8;
                float v0 = gate * gelu_exact(acc[mi][ni][h * 2 + 0] + bb0);
                float v1 = gate * gelu_exact(acc[mi][ni][h * 2 + 1] + bb1);
                __nv_bfloat16 h0 = __float2bfloat16(v0);
                __nv_bfloat16 h1 = __float2bfloat16(v1);
                __nv_bfloat162 hp; hp.x = h0; hp.y = h1;
                *(__nv_bfloat162*)(Hh + (size_t)row * NF + col) = hp;
                __nv_bfloat162 lp;
                lp.x = __float2bfloat16(v0 - __bfloat162float(h0));
                lp.y = __float2bfloat16(v1 - __bfloat162float(h1));
                *(__nv_bfloat162*)(Hl + (size_t)row * NF + col) = lp;
            }
        }
    }
}

// ---------------------------------------------------------------------------
// GEMM2: per (b, ntile): out = sum_{e active} H'_e[128,1536] @ W2'_e[1536,128]
//        + sum_e g_e * b2_e.  Single writer per tile -> no atomics.
// ---------------------------------------------------------------------------
__global__ void __launch_bounds__(256, 2) gemm2_kernel(const float* __restrict__ b2,
                                                       float* __restrict__ out) {
    const int b = blockIdx.x, nt = blockIdx.y;
    const int tid = threadIdx.x, lane = tid & 31, wid = tid >> 5;
    const int wm = wid & 1, wn = wid >> 1;
    const int n0 = nt * 128;

    float gates[NE];
    int act[NE], na = 0;
#pragma unroll
    for (int e = 0; e < NE; e++) {
        gates[e] = g_gates[b * NE + e];
        if (gates[e] != 0.0f) act[na++] = e;
    }
    if (na == 0) {
        float4 z = make_float4(0.f, 0.f, 0.f, 0.f);
        float* o = out + (size_t)b * NL * ND + n0;
        for (int i = tid; i < NL * 32; i += 256) {
            int r = i >> 5, c = (i & 31) << 2;
            *(float4*)(o + (size_t)r * ND + c) = z;
        }
        return;
    }

    __shared__ __align__(128) char sm[SM_TOTAL];
    __shared__ float cb[128];
    const uint32_t smb = smem_u32(sm);

    if (tid < 128) {
        float s = 0.f;
#pragma unroll
        for (int e = 0; e < NE; e++) s += gates[e] * __ldg(b2 + e * ND + n0 + tid);
        cb[tid] = s;
    }

    float acc[4][4][4] = {};
    const int total = na * 48;  // 48 BK-chunks per expert (3 segs x 512/32)

    // chunk i -> e = act[i/48], kc = i%48, seg = kc/16, k = (kc%16)*32
    auto srcs = [&](int i, const __nv_bfloat16*& As, const __nv_bfloat16*& Bs) {
        int e = act[i / 48];
        int kc = i % 48;
        int seg = kc >> 4;
        int k = (kc & 15) << 5;
        const __nv_bfloat16* Ab = (seg == 1) ? g_Hlo : g_Hhi;
        const __nv_bfloat16* Bb = (seg == 2) ? g_W2Tlo : g_W2Thi;
        As = Ab + (size_t)(b * NE + e) * NL * NF + k;
        Bs = Bb + ((size_t)e * ND + n0) * NF + k;
    };

    {
        const __nv_bfloat16 *As, *Bs;
        srcs(0, As, Bs);
        fill_stage(smb, 0, As, NF, Bs, NF, tid);
    }
    for (int i = 0; i < total; i++) {
        CP_WAIT0();
        __syncthreads();
        if (i + 1 < total) {
            const __nv_bfloat16 *As, *Bs;
            srcs(i + 1, As, Bs);
            fill_stage(smb, (i + 1) & 1, As, NF, Bs, NF, tid);
        }
        compute_stage(smb, i & 1, wm, wn, lane, acc);
        __syncthreads();
    }

    // Epilogue: add gate-weighted bias, write fp32 out
    const int r0 = lane >> 2, c0 = (lane & 3) * 2;
#pragma unroll
    for (int mi = 0; mi < 4; mi++) {
#pragma unroll
        for (int ni = 0; ni < 4; ni++) {
            int lc = wn * 32 + ni * 8 + c0;
            float bb0 = cb[lc], bb1 = cb[lc + 1];
#pragma unroll
            for (int h = 0; h < 2; h++) {
                int row = wm * 64 + mi * 16 + r0 + h * 8;
                float* o = out + ((size_t)b * NL + row) * ND + n0 + lc;
                o[0] = acc[mi][ni][h * 2 + 0] + bb0;
                o[1] = acc[mi][ni][h * 2 + 1] + bb1;
            }
        }
    }
}

// ---------------------------------------------------------------------------
extern "C" void kernel_launch(void* const* d_in, const int* in_sizes, int n_in,
                              void* d_out, int out_size) {
    const float* x      = (const float*)d_in[0];
    const float* logits = (const float*)d_in[1];
    const float* W1     = (const float*)d_in[2];
    const float* b1     = (const float*)d_in[3];
    const float* W2     = (const float*)d_in[4];
    const float* b2     = (const float*)d_in[5];
    const int*   masks  = (const int*)d_in[6];
    float* out = (float*)d_out;

    gate_kernel<<<2, 256>>>(logits, masks);
    prep_x<<<1024, 256>>>(x);
    prep_w1<<<512, 256>>>(W1);
    prep_w2<<<512, 256>>>(W2);
    gemm1_kernel<<<dim3(NB, NF / 128, NE), 256>>>(b1);
    gemm2_kernel<<<dim3(NB, ND / 128), 256>>>(b2, out);
}

// round 5
// speedup vs baseline: 2.5506x; 1.1561x over previous
#include <cuda_runtime.h>
#include <cuda_bf16.h>
#include <math.h>
#include <stdint.h>

#define NB 512
#define NL 128
#define ND 256
#define NF 512
#define NE 8

// ---------------------------------------------------------------------------
// Device scratch (allocation-free rule)
// ---------------------------------------------------------------------------
__device__ float g_gates[NB * NE];
__device__ __nv_bfloat16 g_Xhi[(size_t)NB * NL * ND];
__device__ __nv_bfloat16 g_Xlo[(size_t)NB * NL * ND];
__device__ __nv_bfloat16 g_W1Thi[(size_t)NE * NF * ND];   // [e][n][k]
__device__ __nv_bfloat16 g_W1Tlo[(size_t)NE * NF * ND];
__device__ __nv_bfloat16 g_W2Thi[(size_t)NE * ND * NF];   // [e][n][k]
__device__ __nv_bfloat16 g_W2Tlo[(size_t)NE * ND * NF];
__device__ __nv_bfloat16 g_Hhi[(size_t)NB * NE * NL * NF];
__device__ __nv_bfloat16 g_Hlo[(size_t)NB * NE * NL * NF];

// ---------------------------------------------------------------------------
// PTX helpers — baseline (non-'a') features only: cp.async, ldmatrix, mma.sync
// ---------------------------------------------------------------------------
__device__ __forceinline__ uint32_t smem_u32(const void* p) {
    uint32_t a;
    asm("{ .reg .u64 t; cvta.to.shared.u64 t, %1; cvt.u32.u64 %0, t; }" : "=r"(a) : "l"(p));
    return a;
}
__device__ __forceinline__ void cp16(uint32_t dst, const void* src) {
    asm volatile("cp.async.cg.shared.global [%0], [%1], 16;" :: "r"(dst), "l"(src));
}
#define CP_COMMIT() asm volatile("cp.async.commit_group;" ::: "memory")
#define CP_WAIT0()  asm volatile("cp.async.wait_group 0;" ::: "memory")
#define CP_WAIT1()  asm volatile("cp.async.wait_group 1;" ::: "memory")

#define LDSM4(r0, r1, r2, r3, addr) \
    asm volatile("ldmatrix.sync.aligned.m8n8.x4.shared.b16 {%0,%1,%2,%3}, [%4];" \
                 : "=r"(r0), "=r"(r1), "=r"(r2), "=r"(r3) : "r"(addr))

#define MMA16816(c, a, b0, b1) \
    asm volatile("mma.sync.aligned.m16n8k16.row.col.f32.bf16.bf16.f32 " \
                 "{%0,%1,%2,%3}, {%4,%5,%6,%7}, {%8,%9}, {%0,%1,%2,%3};" \
                 : "+f"((c)[0]), "+f"((c)[1]), "+f"((c)[2]), "+f"((c)[3]) \
                 : "r"((a)[0]), "r"((a)[1]), "r"((a)[2]), "r"((a)[3]), \
                   "r"(b0), "r"(b1))

__device__ __forceinline__ float gelu_exact(float v) {
    return 0.5f * v * (1.0f + erff(v * 0.70710678118654752f));
}

// ---------------------------------------------------------------------------
// SMEM geometry: BK=64 tiles [128 rows][64 cols] bf16, row stride 144 BYTES
// (144 mod 128 = 16 -> ldmatrix 8-row phases hit distinct 16B lanes; 16B-aligned
// for cp.async). 3 stages, A+B per stage.
// ---------------------------------------------------------------------------
#define ROW_BYTES 144
#define TILE_BYTES (128 * ROW_BYTES)               // 18432
#define STAGE_BYTES (2 * TILE_BYTES)               // 36864
#define SM_A(st) ((st) * STAGE_BYTES)
#define SM_B(st) ((st) * STAGE_BYTES + TILE_BYTES)
#define SM_TOTAL (3 * STAGE_BYTES)                 // 110592

// Fill one stage (A and B [128 x 64] bf16) via cp.async: 8 x 16B per thread.
__device__ __forceinline__ void fill_stage(uint32_t smb, int st,
                                           const __nv_bfloat16* As, int Astride,
                                           const __nv_bfloat16* Bs, int Bstride,
                                           int tid) {
#pragma unroll
    for (int i = 0; i < 4; i++) {
        int q = tid + i * 256;          // 0..1023, 8 x 16B chunks per row
        int r = q >> 3;
        int c = (q & 7) << 3;           // elem col
        cp16(smb + SM_A(st) + r * ROW_BYTES + c * 2, As + (size_t)r * Astride + c);
    }
#pragma unroll
    for (int i = 0; i < 4; i++) {
        int q = tid + i * 256;
        int r = q >> 3;
        int c = (q & 7) << 3;
        cp16(smb + SM_B(st) + r * ROW_BYTES + c * 2, Bs + (size_t)r * Bstride + c);
    }
    CP_COMMIT();
}

// One BK=64 compute step: per warp 16 A-ldsm.x4 + 8 B-ldsm.x4 + 64 HMMA.
__device__ __forceinline__ void compute_stage(uint32_t smb, int st, int wm, int wn,
                                              int lane, float acc[4][4][4]) {
#pragma unroll
    for (int ks = 0; ks < 4; ks++) {
        uint32_t a[4][4];
#pragma unroll
        for (int mi = 0; mi < 4; mi++) {
            uint32_t ad = smb + SM_A(st) +
                (wm * 64 + mi * 16 + (lane & 15)) * ROW_BYTES + ks * 32 + (lane >> 4) * 16;
            LDSM4(a[mi][0], a[mi][1], a[mi][2], a[mi][3], ad);
        }
        uint32_t bfr[2][4];
        int quad = lane >> 3;
#pragma unroll
        for (int g = 0; g < 2; g++) {
            uint32_t bd = smb + SM_B(st) +
                (wn * 32 + g * 16 + (quad >> 1) * 8 + (lane & 7)) * ROW_BYTES +
                ks * 32 + (quad & 1) * 16;
            LDSM4(bfr[g][0], bfr[g][1], bfr[g][2], bfr[g][3], bd);
        }
#pragma unroll
        for (int mi = 0; mi < 4; mi++)
#pragma unroll
            for (int ni = 0; ni < 4; ni++)
                MMA16816(acc[mi][ni], a[mi],
                         bfr[ni >> 1][(ni & 1) * 2], bfr[ni >> 1][(ni & 1) * 2 + 1]);
    }
}

// ---------------------------------------------------------------------------
// Prep kernels
// ---------------------------------------------------------------------------
__global__ void gate_kernel(const float* __restrict__ logits, const int* __restrict__ masks) {
    int b = blockIdx.x * blockDim.x + threadIdx.x;
    if (b >= NB) return;
    float v[NE]; float mx = -1e30f;
#pragma unroll
    for (int e = 0; e < NE; e++) { v[e] = logits[b * NE + e]; mx = fmaxf(mx, v[e]); }
    float s = 0.f;
#pragma unroll
    for (int e = 0; e < NE; e++) { v[e] = expf(v[e] - mx); s += v[e]; }
    float inv = 1.f / s; float gs = 0.f;
#pragma unroll
    for (int e = 0; e < NE; e++) { v[e] = (masks[b * NE + e] == 1) ? v[e] * inv : 0.f; gs += v[e]; }
    float d = 1.f / (gs + 1e-9f);
#pragma unroll
    for (int e = 0; e < NE; e++) g_gates[b * NE + e] = v[e] * d;
}

__global__ void prep_x(const float* __restrict__ x) {
    size_t n = (size_t)NB * NL * ND;
    for (size_t i = blockIdx.x * (size_t)blockDim.x + threadIdx.x; i < n;
         i += (size_t)gridDim.x * blockDim.x) {
        float v = x[i];
        __nv_bfloat16 hi = __float2bfloat16(v);
        g_Xhi[i] = hi;
        g_Xlo[i] = __float2bfloat16(v - __bfloat162float(hi));
    }
}
__global__ void prep_w1(const float* __restrict__ W1) {
    int n = NE * NF * ND;
    for (int i = blockIdx.x * blockDim.x + threadIdx.x; i < n; i += gridDim.x * blockDim.x) {
        int e = i / (NF * ND), r = i % (NF * ND);
        int nn = r / ND, k = r % ND;
        float v = W1[(size_t)e * ND * NF + (size_t)k * NF + nn];
        __nv_bfloat16 hi = __float2bfloat16(v);
        g_W1Thi[i] = hi;
        g_W1Tlo[i] = __float2bfloat16(v - __bfloat162float(hi));
    }
}
__global__ void prep_w2(const float* __restrict__ W2) {
    int n = NE * ND * NF;
    for (int i = blockIdx.x * blockDim.x + threadIdx.x; i < n; i += gridDim.x * blockDim.x) {
        int e = i / (ND * NF), r = i % (ND * NF);
        int nn = r / NF, k = r % NF;
        float v = W2[(size_t)e * NF * ND + (size_t)k * ND + nn];
        __nv_bfloat16 hi = __float2bfloat16(v);
        g_W2Thi[i] = hi;
        g_W2Tlo[i] = __float2bfloat16(v - __bfloat162float(hi));
    }
}

// ---------------------------------------------------------------------------
// GEMM1: per active (b, nt, e): D = X'[128, 768] @ W1'[768, 128]
// K' segs of 256 (4 BK=64 chunks): {Ahi*Bhi, Alo*Bhi, Ahi*Blo}.
// Epilogue: gate*gelu(D + b1), split to bf16 hi/lo, staged via SMEM for
// coalesced 16B stores.
// ---------------------------------------------------------------------------
__global__ void __launch_bounds__(256, 2) gemm1_kernel(const float* __restrict__ b1) {
    const int b = blockIdx.x, nt = blockIdx.y, e = blockIdx.z;
    const float gate = g_gates[b * NE + e];
    if (gate == 0.0f) return;

    extern __shared__ __align__(128) char sm[];
    const uint32_t smb = smem_u32(sm);
    const int tid = threadIdx.x, lane = tid & 31, wid = tid >> 5;
    const int wm = wid & 1, wn = wid >> 1;

    const __nv_bfloat16* Ah = g_Xhi + (size_t)b * NL * ND;
    const __nv_bfloat16* Al = g_Xlo + (size_t)b * NL * ND;
    const __nv_bfloat16* Bh = g_W1Thi + ((size_t)e * NF + nt * 128) * ND;
    const __nv_bfloat16* Bl = g_W1Tlo + ((size_t)e * NF + nt * 128) * ND;
    const __nv_bfloat16* Aseg[3] = {Ah, Al, Ah};
    const __nv_bfloat16* Bseg[3] = {Bh, Bh, Bl};

    float acc[4][4][4] = {};
    const int total = 12;  // 3 segs x 4 BK=64 chunks

    fill_stage(smb, 0, Aseg[0], ND, Bseg[0], ND, tid);
    fill_stage(smb, 1, Aseg[0] + 64, ND, Bseg[0] + 64, ND, tid);
    for (int i = 0; i < total; i++) {
        if (i + 1 < total) { CP_WAIT1(); } else { CP_WAIT0(); }
        __syncthreads();
        if (i + 2 < total) {
            int kn = i + 2;
            int seg = kn >> 2, k = (kn & 3) << 6;
            fill_stage(smb, kn % 3, Aseg[seg] + k, ND, Bseg[seg] + k, ND, tid);
        }
        compute_stage(smb, i % 3, wm, wn, lane, acc);
        __syncthreads();
    }

    // Epilogue: stage gated-GELU hi/lo bf16 tiles in SMEM, then coalesced write.
    // Shi/Slo: [128][128] bf16, row stride 272 bytes (16B aligned, bank-rotating)
    const uint32_t shi = smb;
    const uint32_t slo = smb + 128 * 272;
    const int r0 = lane >> 2, c0 = (lane & 3) * 2;
#pragma unroll
    for (int mi = 0; mi < 4; mi++) {
#pragma unroll
        for (int ni = 0; ni < 4; ni++) {
            int lc = wn * 32 + ni * 8 + c0;
            float bb0 = __ldg(b1 + e * NF + nt * 128 + lc);
            float bb1 = __ldg(b1 + e * NF + nt * 128 + lc + 1);
#pragma unroll
            for (int h = 0; h < 2; h++) {
                int row = wm * 64 + mi * 16 + r0 + h * 8;
                float v0 = gate * gelu_exact(acc[mi][ni][h * 2 + 0] + bb0);
                float v1 = gate * gelu_exact(acc[mi][ni][h * 2 + 1] + bb1);
                __nv_bfloat16 h0 = __float2bfloat16(v0);
                __nv_bfloat16 h1 = __float2bfloat16(v1);
                uint32_t hp = (uint32_t)__bfloat16_as_ushort(h0) |
                              ((uint32_t)__bfloat16_as_ushort(h1) << 16);
                __nv_bfloat16 l0 = __float2bfloat16(v0 - __bfloat162float(h0));
                __nv_bfloat16 l1 = __float2bfloat16(v1 - __bfloat162float(h1));
                uint32_t lp = (uint32_t)__bfloat16_as_ushort(l0) |
                              ((uint32_t)__bfloat16_as_ushort(l1) << 16);
                uint32_t off = row * 272 + lc * 2;
                asm volatile("st.shared.b32 [%0], %1;" :: "r"(shi + off), "r"(hp));
                asm volatile("st.shared.b32 [%0], %1;" :: "r"(slo + off), "r"(lp));
            }
        }
    }
    __syncthreads();

    __nv_bfloat16* Hh = g_Hhi + (size_t)(b * NE + e) * NL * NF + nt * 128;
    __nv_bfloat16* Hl = g_Hlo + (size_t)(b * NE + e) * NL * NF + nt * 128;
#pragma unroll
    for (int it = 0; it < 8; it++) {
        int idx = tid + it * 256;       // 128 rows x 16 16B-units
        int row = idx >> 4;
        int u = idx & 15;
        float4 vh, vl;
        asm volatile("ld.shared.v4.b32 {%0,%1,%2,%3}, [%4];"
                     : "=f"(vh.x), "=f"(vh.y), "=f"(vh.z), "=f"(vh.w)
                     : "r"(shi + row * 272 + u * 16));
        asm volatile("ld.shared.v4.b32 {%0,%1,%2,%3}, [%4];"
                     : "=f"(vl.x), "=f"(vl.y), "=f"(vl.z), "=f"(vl.w)
                     : "r"(slo + row * 272 + u * 16));
        *(float4*)(Hh + (size_t)row * NF + u * 8) = vh;
        *(float4*)(Hl + (size_t)row * NF + u * 8) = vl;
    }
}

// ---------------------------------------------------------------------------
// GEMM2: per (b, nt): out = sum_{e active} H'_e[128,1536] @ W2'_e[1536,128]
//        + sum_e g_e * b2_e.  Single writer per tile -> no atomics.
// ---------------------------------------------------------------------------
__global__ void __launch_bounds__(256, 2) gemm2_kernel(const float* __restrict__ b2,
                                                       float* __restrict__ out) {
    const int b = blockIdx.x, nt = blockIdx.y;
    const int tid = threadIdx.x, lane = tid & 31, wid = tid >> 5;
    const int wm = wid & 1, wn = wid >> 1;
    const int n0 = nt * 128;

    float gates[NE];
    int act[NE], na = 0;
#pragma unroll
    for (int e = 0; e < NE; e++) {
        gates[e] = g_gates[b * NE + e];
        if (gates[e] != 0.0f) act[na++] = e;
    }
    if (na == 0) {
        float4 z = make_float4(0.f, 0.f, 0.f, 0.f);
        float* o = out + (size_t)b * NL * ND + n0;
        for (int i = tid; i < NL * 32; i += 256) {
            int r = i >> 5, c = (i & 31) << 2;
            *(float4*)(o + (size_t)r * ND + c) = z;
        }
        return;
    }

    extern __shared__ __align__(128) char sm[];
    __shared__ float cb[128];
    const uint32_t smb = smem_u32(sm);

    if (tid < 128) {
        float s = 0.f;
#pragma unroll
        for (int e = 0; e < NE; e++) s += gates[e] * __ldg(b2 + e * ND + n0 + tid);
        cb[tid] = s;
    }

    float acc[4][4][4] = {};
    const int total = na * 24;  // per expert: 3 segs x 8 BK=64 chunks

    // chunk i -> e = act[i/24], kc = i%24, seg = kc/8, k = (kc%8)*64
    auto srcs = [&](int i, const __nv_bfloat16*& As, const __nv_bfloat16*& Bs) {
        int e = act[i / 24];
        int kc = i % 24;
        int seg = kc >> 3;
        int k = (kc & 7) << 6;
        const __nv_bfloat16* Ab = (seg == 1) ? g_Hlo : g_Hhi;
        const __nv_bfloat16* Bb = (seg == 2) ? g_W2Tlo : g_W2Thi;
        As = Ab + (size_t)(b * NE + e) * NL * NF + k;
        Bs = Bb + ((size_t)e * ND + n0) * NF + k;
    };

    {
        const __nv_bfloat16 *As, *Bs;
        srcs(0, As, Bs);
        fill_stage(smb, 0, As, NF, Bs, NF, tid);
        srcs(1, As, Bs);
        fill_stage(smb, 1, As, NF, Bs, NF, tid);
    }
    for (int i = 0; i < total; i++) {
        if (i + 1 < total) { CP_WAIT1(); } else { CP_WAIT0(); }
        __syncthreads();
        if (i + 2 < total) {
            const __nv_bfloat16 *As, *Bs;
            srcs(i + 2, As, Bs);
            fill_stage(smb, (i + 2) % 3, As, NF, Bs, NF, tid);
        }
        compute_stage(smb, i % 3, wm, wn, lane, acc);
        __syncthreads();
    }

    // Epilogue: add gate-weighted bias, write fp32 out (67 MB total -> direct)
    const int r0 = lane >> 2, c0 = (lane & 3) * 2;
#pragma unroll
    for (int mi = 0; mi < 4; mi++) {
#pragma unroll
        for (int ni = 0; ni < 4; ni++) {
            int lc = wn * 32 + ni * 8 + c0;
            float bb0 = cb[lc], bb1 = cb[lc + 1];
#pragma unroll
            for (int h = 0; h < 2; h++) {
                int row = wm * 64 + mi * 16 + r0 + h * 8;
                float* o = out + ((size_t)b * NL + row) * ND + n0 + lc;
                float2 v = make_float2(acc[mi][ni][h * 2 + 0] + bb0,
                                       acc[mi][ni][h * 2 + 1] + bb1);
                *(float2*)o = v;
            }
        }
    }
}

// ---------------------------------------------------------------------------
extern "C" void kernel_launch(void* const* d_in, const int* in_sizes, int n_in,
                              void* d_out, int out_size) {
    const float* x      = (const float*)d_in[0];
    const float* logits = (const float*)d_in[1];
    const float* W1     = (const float*)d_in[2];
    const float* b1     = (const float*)d_in[3];
    const float* W2     = (const float*)d_in[4];
    const float* b2     = (const float*)d_in[5];
    const int*   masks  = (const int*)d_in[6];
    float* out = (float*)d_out;

    cudaFuncSetAttribute(gemm1_kernel, cudaFuncAttributeMaxDynamicSharedMemorySize, SM_TOTAL);
    cudaFuncSetAttribute(gemm2_kernel, cudaFuncAttributeMaxDynamicSharedMemorySize, SM_TOTAL);

    gate_kernel<<<2, 256>>>(logits, masks);
    prep_x<<<1024, 256>>>(x);
    prep_w1<<<512, 256>>>(W1);
    prep_w2<<<512, 256>>>(W2);
    gemm1_kernel<<<dim3(NB, NF / 128, NE), 256, SM_TOTAL>>>(b1);
    gemm2_kernel<<<dim3(NB, ND / 128), 256, SM_TOTAL>>>(b2, out);
}

// round 6
// speedup vs baseline: 6.3109x; 2.4743x over previous
#include <cuda_runtime.h>
#include <cuda_fp16.h>
#include <math.h>
#include <stdint.h>

#define NB 512
#define NL 128
#define ND 256
#define NF 512
#define NE 8

// ---------------------------------------------------------------------------
// Device scratch (allocation-free rule)
// ---------------------------------------------------------------------------
__device__ float g_gates[NB * NE];
__device__ __half g_Xh[(size_t)NB * NL * ND];
__device__ __half g_W1T[(size_t)NE * NF * ND];   // [e][n][k]
__device__ __half g_W2T[(size_t)NE * ND * NF];   // [e][n][k]
__device__ __half g_H[(size_t)NB * NE * NL * NF];

// ---------------------------------------------------------------------------
// PTX helpers — baseline (non-'a') features only: cp.async, ldmatrix, mma.sync
// ---------------------------------------------------------------------------
__device__ __forceinline__ uint32_t smem_u32(const void* p) {
    uint32_t a;
    asm("{ .reg .u64 t; cvta.to.shared.u64 t, %1; cvt.u32.u64 %0, t; }" : "=r"(a) : "l"(p));
    return a;
}
__device__ __forceinline__ void cp16(uint32_t dst, const void* src) {
    asm volatile("cp.async.cg.shared.global [%0], [%1], 16;" :: "r"(dst), "l"(src));
}
#define CP_COMMIT() asm volatile("cp.async.commit_group;" ::: "memory")
#define CP_WAIT0()  asm volatile("cp.async.wait_group 0;" ::: "memory")
#define CP_WAIT1()  asm volatile("cp.async.wait_group 1;" ::: "memory")

#define LDSM4(r0, r1, r2, r3, addr) \
    asm volatile("ldmatrix.sync.aligned.m8n8.x4.shared.b16 {%0,%1,%2,%3}, [%4];" \
                 : "=r"(r0), "=r"(r1), "=r"(r2), "=r"(r3) : "r"(addr))

#define MMA16816(c, a, b0, b1) \
    asm volatile("mma.sync.aligned.m16n8k16.row.col.f32.f16.f16.f32 " \
                 "{%0,%1,%2,%3}, {%4,%5,%6,%7}, {%8,%9}, {%0,%1,%2,%3};" \
                 : "+f"((c)[0]), "+f"((c)[1]), "+f"((c)[2]), "+f"((c)[3]) \
                 : "r"((a)[0]), "r"((a)[1]), "r"((a)[2]), "r"((a)[3]), \
                   "r"(b0), "r"(b1))

__device__ __forceinline__ float gelu_exact(float v) {
    return 0.5f * v * (1.0f + erff(v * 0.70710678118654752f));
}

// ---------------------------------------------------------------------------
// SMEM geometry: BK=64 tiles [128 rows][64 cols] f16, row stride 144 BYTES.
// 3 stages, A+B per stage.
// ---------------------------------------------------------------------------
#define ROW_BYTES 144
#define TILE_BYTES (128 * ROW_BYTES)               // 18432
#define STAGE_BYTES (2 * TILE_BYTES)               // 36864
#define SM_A(st) ((st) * STAGE_BYTES)
#define SM_B(st) ((st) * STAGE_BYTES + TILE_BYTES)
#define SM_TOTAL (3 * STAGE_BYTES)                 // 110592

// Fill one stage (A and B [128 x 64] f16) via cp.async: 8 x 16B per thread.
__device__ __forceinline__ void fill_stage(uint32_t smb, int st,
                                           const __half* As, int Astride,
                                           const __half* Bs, int Bstride,
                                           int tid) {
#pragma unroll
    for (int i = 0; i < 4; i++) {
        int q = tid + i * 256;
        int r = q >> 3;
        int c = (q & 7) << 3;
        cp16(smb + SM_A(st) + r * ROW_BYTES + c * 2, As + (size_t)r * Astride + c);
    }
#pragma unroll
    for (int i = 0; i < 4; i++) {
        int q = tid + i * 256;
        int r = q >> 3;
        int c = (q & 7) << 3;
        cp16(smb + SM_B(st) + r * ROW_BYTES + c * 2, Bs + (size_t)r * Bstride + c);
    }
    CP_COMMIT();
}

// One BK=64 compute step: per warp 16 A-ldsm.x4 + 8 B-ldsm.x4 + 64 HMMA.
__device__ __forceinline__ void compute_stage(uint32_t smb, int st, int wm, int wn,
                                              int lane, float acc[4][4][4]) {
#pragma unroll
    for (int ks = 0; ks < 4; ks++) {
        uint32_t a[4][4];
#pragma unroll
        for (int mi = 0; mi < 4; mi++) {
            uint32_t ad = smb + SM_A(st) +
                (wm * 64 + mi * 16 + (lane & 15)) * ROW_BYTES + ks * 32 + (lane >> 4) * 16;
            LDSM4(a[mi][0], a[mi][1], a[mi][2], a[mi][3], ad);
        }
        uint32_t bfr[2][4];
        int quad = lane >> 3;
#pragma unroll
        for (int g = 0; g < 2; g++) {
            uint32_t bd = smb + SM_B(st) +
                (wn * 32 + g * 16 + (quad >> 1) * 8 + (lane & 7)) * ROW_BYTES +
                ks * 32 + (quad & 1) * 16;
            LDSM4(bfr[g][0], bfr[g][1], bfr[g][2], bfr[g][3], bd);
        }
#pragma unroll
        for (int mi = 0; mi < 4; mi++)
#pragma unroll
            for (int ni = 0; ni < 4; ni++)
                MMA16816(acc[mi][ni], a[mi],
                         bfr[ni >> 1][(ni & 1) * 2], bfr[ni >> 1][(ni & 1) * 2 + 1]);
    }
}

// ---------------------------------------------------------------------------
// Prep kernels
// ---------------------------------------------------------------------------
__global__ void gate_kernel(const float* __restrict__ logits, const int* __restrict__ masks) {
    int b = blockIdx.x * blockDim.x + threadIdx.x;
    if (b >= NB) return;
    float v[NE]; float mx = -1e30f;
#pragma unroll
    for (int e = 0; e < NE; e++) { v[e] = logits[b * NE + e]; mx = fmaxf(mx, v[e]); }
    float s = 0.f;
#pragma unroll
    for (int e = 0; e < NE; e++) { v[e] = expf(v[e] - mx); s += v[e]; }
    float inv = 1.f / s; float gs = 0.f;
#pragma unroll
    for (int e = 0; e < NE; e++) { v[e] = (masks[b * NE + e] == 1) ? v[e] * inv : 0.f; gs += v[e]; }
    float d = 1.f / (gs + 1e-9f);
#pragma unroll
    for (int e = 0; e < NE; e++) g_gates[b * NE + e] = v[e] * d;
}

__global__ void prep_x(const float* __restrict__ x) {
    size_t n = (size_t)NB * NL * ND;
    for (size_t i = blockIdx.x * (size_t)blockDim.x + threadIdx.x; i < n;
         i += (size_t)gridDim.x * blockDim.x) {
        g_Xh[i] = __float2half(x[i]);
    }
}
__global__ void prep_w1(const float* __restrict__ W1) {
    int n = NE * NF * ND;
    for (int i = blockIdx.x * blockDim.x + threadIdx.x; i < n; i += gridDim.x * blockDim.x) {
        int e = i / (NF * ND), r = i % (NF * ND);
        int nn = r / ND, k = r % ND;
        g_W1T[i] = __float2half(W1[(size_t)e * ND * NF + (size_t)k * NF + nn]);
    }
}
__global__ void prep_w2(const float* __restrict__ W2) {
    int n = NE * ND * NF;
    for (int i = blockIdx.x * blockDim.x + threadIdx.x; i < n; i += gridDim.x * blockDim.x) {
        int e = i / (ND * NF), r = i % (ND * NF);
        int nn = r / NF, k = r % NF;
        g_W2T[i] = __float2half(W2[(size_t)e * NF * ND + (size_t)k * ND + nn]);
    }
}

// ---------------------------------------------------------------------------
// GEMM1: per active (b, nt, e): D = X[128,256] @ W1T[.,256]^T (fp16 single).
// Epilogue: H = gate * gelu(D + b1) -> fp16, SMEM-staged coalesced stores.
// ---------------------------------------------------------------------------
__global__ void __launch_bounds__(256, 2) gemm1_kernel(const float* __restrict__ b1) {
    const int b = blockIdx.x, nt = blockIdx.y, e = blockIdx.z;
    const float gate = g_gates[b * NE + e];
    if (gate == 0.0f) return;

    extern __shared__ __align__(128) char sm[];
    const uint32_t smb = smem_u32(sm);
    const int tid = threadIdx.x, lane = tid & 31, wid = tid >> 5;
    const int wm = wid & 1, wn = wid >> 1;

    const __half* A = g_Xh + (size_t)b * NL * ND;
    const __half* B = g_W1T + ((size_t)e * NF + nt * 128) * ND;

    float acc[4][4][4] = {};
    const int total = 4;  // 4 BK=64 chunks over K=256

    fill_stage(smb, 0, A, ND, B, ND, tid);
    fill_stage(smb, 1, A + 64, ND, B + 64, ND, tid);
    for (int i = 0; i < total; i++) {
        if (i + 1 < total) { CP_WAIT1(); } else { CP_WAIT0(); }
        __syncthreads();
        if (i + 2 < total) {
            int k = (i + 2) << 6;
            fill_stage(smb, (i + 2) % 3, A + k, ND, B + k, ND, tid);
        }
        compute_stage(smb, i % 3, wm, wn, lane, acc);
        __syncthreads();
    }

    // Epilogue: stage gated-GELU fp16 tile in SMEM, then coalesced 16B writes.
    const uint32_t sh = smb;  // [128][128] f16, row stride 272 B
    const int r0 = lane >> 2, c0 = (lane & 3) * 2;
#pragma unroll
    for (int mi = 0; mi < 4; mi++) {
#pragma unroll
        for (int ni = 0; ni < 4; ni++) {
            int lc = wn * 32 + ni * 8 + c0;
            float bb0 = __ldg(b1 + e * NF + nt * 128 + lc);
            float bb1 = __ldg(b1 + e * NF + nt * 128 + lc + 1);
#pragma unroll
            for (int h = 0; h < 2; h++) {
                int row = wm * 64 + mi * 16 + r0 + h * 8;
                float v0 = gate * gelu_exact(acc[mi][ni][h * 2 + 0] + bb0);
                float v1 = gate * gelu_exact(acc[mi][ni][h * 2 + 1] + bb1);
                __half h0 = __float2half(v0);
                __half h1 = __float2half(v1);
                uint32_t hp = (uint32_t)__half_as_ushort(h0) |
                              ((uint32_t)__half_as_ushort(h1) << 16);
                asm volatile("st.shared.b32 [%0], %1;" :: "r"(sh + row * 272 + lc * 2), "r"(hp));
            }
        }
    }
    __syncthreads();

    __half* Hp = g_H + (size_t)(b * NE + e) * NL * NF + nt * 128;
#pragma unroll
    for (int it = 0; it < 8; it++) {
        int idx = tid + it * 256;       // 128 rows x 16 16B-units
        int row = idx >> 4;
        int u = idx & 15;
        float4 vh;
        asm volatile("ld.shared.v4.b32 {%0,%1,%2,%3}, [%4];"
                     : "=f"(vh.x), "=f"(vh.y), "=f"(vh.z), "=f"(vh.w)
                     : "r"(sh + row * 272 + u * 16));
        *(float4*)(Hp + (size_t)row * NF + u * 8) = vh;
    }
}

// ---------------------------------------------------------------------------
// GEMM2: per (b, nt): out = sum_{e active} H_e[128,512] @ W2T_e[.,512]^T
//        + sum_e g_e * b2_e.  fp16 single-product; single writer per tile.
// ---------------------------------------------------------------------------
__global__ void __launch_bounds__(256, 2) gemm2_kernel(const float* __restrict__ b2,
                                                       float* __restrict__ out) {
    const int b = blockIdx.x, nt = blockIdx.y;
    const int tid = threadIdx.x, lane = tid & 31, wid = tid >> 5;
    const int wm = wid & 1, wn = wid >> 1;
    const int n0 = nt * 128;

    float gates[NE];
    int act[NE], na = 0;
#pragma unroll
    for (int e = 0; e < NE; e++) {
        gates[e] = g_gates[b * NE + e];
        if (gates[e] != 0.0f) act[na++] = e;
    }
    if (na == 0) {
        float4 z = make_float4(0.f, 0.f, 0.f, 0.f);
        float* o = out + (size_t)b * NL * ND + n0;
        for (int i = tid; i < NL * 32; i += 256) {
            int r = i >> 5, c = (i & 31) << 2;
            *(float4*)(o + (size_t)r * ND + c) = z;
        }
        return;
    }

    extern __shared__ __align__(128) char sm[];
    __shared__ float cb[128];
    const uint32_t smb = smem_u32(sm);

    if (tid < 128) {
        float s = 0.f;
#pragma unroll
        for (int e = 0; e < NE; e++) s += gates[e] * __ldg(b2 + e * ND + n0 + tid);
        cb[tid] = s;
    }

    float acc[4][4][4] = {};
    const int total = na * 8;  // per expert: 8 BK=64 chunks over K=512

    auto srcs = [&](int i, const __half*& As, const __half*& Bs) {
        int e = act[i >> 3];
        int k = (i & 7) << 6;
        As = g_H + (size_t)(b * NE + e) * NL * NF + k;
        Bs = g_W2T + ((size_t)e * ND + n0) * NF + k;
    };

    {
        const __half *As, *Bs;
        srcs(0, As, Bs);
        fill_stage(smb, 0, As, NF, Bs, NF, tid);
        srcs(1, As, Bs);
        fill_stage(smb, 1, As, NF, Bs, NF, tid);
    }
    for (int i = 0; i < total; i++) {
        if (i + 1 < total) { CP_WAIT1(); } else { CP_WAIT0(); }
        __syncthreads();
        if (i + 2 < total) {
            const __half *As, *Bs;
            srcs(i + 2, As, Bs);
            fill_stage(smb, (i + 2) % 3, As, NF, Bs, NF, tid);
        }
        compute_stage(smb, i % 3, wm, wn, lane, acc);
        __syncthreads();
    }

    // Epilogue: add gate-weighted bias, write fp32 out
    const int r0 = lane >> 2, c0 = (lane & 3) * 2;
#pragma unroll
    for (int mi = 0; mi < 4; mi++) {
#pragma unroll
        for (int ni = 0; ni < 4; ni++) {
            int lc = wn * 32 + ni * 8 + c0;
            float bb0 = cb[lc], bb1 = cb[lc + 1];
#pragma unroll
            for (int h = 0; h < 2; h++) {
                int row = wm * 64 + mi * 16 + r0 + h * 8;
                float* o = out + ((size_t)b * NL + row) * ND + n0 + lc;
                float2 v = make_float2(acc[mi][ni][h * 2 + 0] + bb0,
                                       acc[mi][ni][h * 2 + 1] + bb1);
                *(float2*)o = v;
            }
        }
    }
}

// ---------------------------------------------------------------------------
extern "C" void kernel_launch(void* const* d_in, const int* in_sizes, int n_in,
                              void* d_out, int out_size) {
    const float* x      = (const float*)d_in[0];
    const float* logits = (const float*)d_in[1];
    const float* W1     = (const float*)d_in[2];
    const float* b1     = (const float*)d_in[3];
    const float* W2     = (const float*)d_in[4];
    const float* b2     = (const float*)d_in[5];
    const int*   masks  = (const int*)d_in[6];
    float* out = (float*)d_out;

    cudaFuncSetAttribute(gemm1_kernel, cudaFuncAttributeMaxDynamicSharedMemorySize, SM_TOTAL);
    cudaFuncSetAttribute(gemm2_kernel, cudaFuncAttributeMaxDynamicSharedMemorySize, SM_TOTAL);

    gate_kernel<<<2, 256>>>(logits, masks);
    prep_x<<<1024, 256>>>(x);
    prep_w1<<<512, 256>>>(W1);
    prep_w2<<<512, 256>>>(W2);
    gemm1_kernel<<<dim3(NB, NF / 128, NE), 256, SM_TOTAL>>>(b1);
    gemm2_kernel<<<dim3(NB, ND / 128), 256, SM_TOTAL>>>(b2, out);
}

// round 7
// speedup vs baseline: 6.6337x; 1.0512x over previous
#include <cuda_runtime.h>
#include <cuda_fp16.h>
#include <math.h>
#include <stdint.h>

#define NB 512
#define NL 128
#define ND 256
#define NF 512
#define NE 8

// ---------------------------------------------------------------------------
// Device scratch (allocation-free rule)
// ---------------------------------------------------------------------------
__device__ float g_gates[NB * NE];
__device__ __half g_Xh[(size_t)NB * NL * ND];
__device__ __half g_W1T[(size_t)NE * NF * ND];   // [e][n][k]
__device__ __half g_W2T[(size_t)NE * ND * NF];   // [e][n][k]
__device__ __half g_H[(size_t)NB * NE * NL * NF];

// ---------------------------------------------------------------------------
// PTX helpers — baseline (non-'a') features only: cp.async, ldmatrix, mma.sync
// ---------------------------------------------------------------------------
__device__ __forceinline__ uint32_t smem_u32(const void* p) {
    uint32_t a;
    asm("{ .reg .u64 t; cvta.to.shared.u64 t, %1; cvt.u32.u64 %0, t; }" : "=r"(a) : "l"(p));
    return a;
}
__device__ __forceinline__ void cp16(uint32_t dst, const void* src) {
    asm volatile("cp.async.cg.shared.global [%0], [%1], 16;" :: "r"(dst), "l"(src));
}
#define CP_COMMIT() asm volatile("cp.async.commit_group;" ::: "memory")
#define CP_WAIT0()  asm volatile("cp.async.wait_group 0;" ::: "memory")
#define CP_WAIT1()  asm volatile("cp.async.wait_group 1;" ::: "memory")

#define LDSM4(r0, r1, r2, r3, addr) \
    asm volatile("ldmatrix.sync.aligned.m8n8.x4.shared.b16 {%0,%1,%2,%3}, [%4];" \
                 : "=r"(r0), "=r"(r1), "=r"(r2), "=r"(r3) : "r"(addr))

#define MMA16816(c, a, b0, b1) \
    asm volatile("mma.sync.aligned.m16n8k16.row.col.f32.f16.f16.f32 " \
                 "{%0,%1,%2,%3}, {%4,%5,%6,%7}, {%8,%9}, {%0,%1,%2,%3};" \
                 : "+f"((c)[0]), "+f"((c)[1]), "+f"((c)[2]), "+f"((c)[3]) \
                 : "r"((a)[0]), "r"((a)[1]), "r"((a)[2]), "r"((a)[3]), \
                   "r"(b0), "r"(b1))

__device__ __forceinline__ float gelu_exact(float v) {
    return 0.5f * v * (1.0f + erff(v * 0.70710678118654752f));
}

// ---------------------------------------------------------------------------
// Tile geometry
// ---------------------------------------------------------------------------
#define ROW_BYTES 144                               // streamed 64-col tiles
#define TILE_BYTES (128 * ROW_BYTES)                // 18432
// GEMM1 SMEM: X resident [128][264] f16 (stride 528B) + 2 B stages
#define X_STRIDE 528
#define G1_X 0
#define G1_B(st) (67584 + (st) * TILE_BYTES)
#define G1_SMEM (67584 + 2 * TILE_BYTES)            // 104448
// GEMM2 SMEM: 3 stages x (A+B)
#define STAGE_BYTES (2 * TILE_BYTES)                // 36864
#define SM_A(st) ((st) * STAGE_BYTES)
#define SM_B(st) ((st) * STAGE_BYTES + TILE_BYTES)
#define G2_SMEM (3 * STAGE_BYTES)                   // 110592

// Fill a [128 x 64] f16 tile (stride ROW_BYTES) via cp.async: 4 x 16B/thread.
__device__ __forceinline__ void fill_tile(uint32_t dst, const __half* src,
                                          int stride, int tid) {
#pragma unroll
    for (int i = 0; i < 4; i++) {
        int q = tid + i * 256;
        int r = q >> 3;
        int c = (q & 7) << 3;
        cp16(dst + r * ROW_BYTES + c * 2, src + (size_t)r * stride + c);
    }
}

// GEMM2-style compute: A and B both in streamed tiles.
__device__ __forceinline__ void compute_stage(uint32_t smb, int st, int wm, int wn,
                                              int lane, float acc[4][4][4]) {
#pragma unroll
    for (int ks = 0; ks < 4; ks++) {
        uint32_t a[4][4];
#pragma unroll
        for (int mi = 0; mi < 4; mi++) {
            uint32_t ad = smb + SM_A(st) +
                (wm * 64 + mi * 16 + (lane & 15)) * ROW_BYTES + ks * 32 + (lane >> 4) * 16;
            LDSM4(a[mi][0], a[mi][1], a[mi][2], a[mi][3], ad);
        }
        uint32_t bfr[2][4];
        int quad = lane >> 3;
#pragma unroll
        for (int g = 0; g < 2; g++) {
            uint32_t bd = smb + SM_B(st) +
                (wn * 32 + g * 16 + (quad >> 1) * 8 + (lane & 7)) * ROW_BYTES +
                ks * 32 + (quad & 1) * 16;
            LDSM4(bfr[g][0], bfr[g][1], bfr[g][2], bfr[g][3], bd);
        }
#pragma unroll
        for (int mi = 0; mi < 4; mi++)
#pragma unroll
            for (int ni = 0; ni < 4; ni++)
                MMA16816(acc[mi][ni], a[mi],
                         bfr[ni >> 1][(ni & 1) * 2], bfr[ni >> 1][(ni & 1) * 2 + 1]);
    }
}

// GEMM1 compute: A from resident X (stride 528B, chunk kc), B from streamed tile.
__device__ __forceinline__ void compute_xres(uint32_t smb, uint32_t bst, int kc,
                                             int wm, int wn, int lane,
                                             float acc[4][4][4]) {
#pragma unroll
    for (int ks = 0; ks < 4; ks++) {
        uint32_t a[4][4];
#pragma unroll
        for (int mi = 0; mi < 4; mi++) {
            uint32_t ad = smb + G1_X +
                (wm * 64 + mi * 16 + (lane & 15)) * X_STRIDE + kc * 128 + ks * 32 +
                (lane >> 4) * 16;
            LDSM4(a[mi][0], a[mi][1], a[mi][2], a[mi][3], ad);
        }
        uint32_t bfr[2][4];
        int quad = lane >> 3;
#pragma unroll
        for (int g = 0; g < 2; g++) {
            uint32_t bd = bst +
                (wn * 32 + g * 16 + (quad >> 1) * 8 + (lane & 7)) * ROW_BYTES +
                ks * 32 + (quad & 1) * 16;
            LDSM4(bfr[g][0], bfr[g][1], bfr[g][2], bfr[g][3], bd);
        }
#pragma unroll
        for (int mi = 0; mi < 4; mi++)
#pragma unroll
            for (int ni = 0; ni < 4; ni++)
                MMA16816(acc[mi][ni], a[mi],
                         bfr[ni >> 1][(ni & 1) * 2], bfr[ni >> 1][(ni & 1) * 2 + 1]);
    }
}

// ---------------------------------------------------------------------------
// Prep kernels (coalesced)
// ---------------------------------------------------------------------------
__global__ void gate_kernel(const float* __restrict__ logits, const int* __restrict__ masks) {
    int b = blockIdx.x * blockDim.x + threadIdx.x;
    if (b >= NB) return;
    float v[NE]; float mx = -1e30f;
#pragma unroll
    for (int e = 0; e < NE; e++) { v[e] = logits[b * NE + e]; mx = fmaxf(mx, v[e]); }
    float s = 0.f;
#pragma unroll
    for (int e = 0; e < NE; e++) { v[e] = expf(v[e] - mx); s += v[e]; }
    float inv = 1.f / s; float gs = 0.f;
#pragma unroll
    for (int e = 0; e < NE; e++) { v[e] = (masks[b * NE + e] == 1) ? v[e] * inv : 0.f; gs += v[e]; }
    float d = 1.f / (gs + 1e-9f);
#pragma unroll
    for (int e = 0; e < NE; e++) g_gates[b * NE + e] = v[e] * d;
}

__global__ void prep_x(const float* __restrict__ x) {
    size_t i0 = ((size_t)blockIdx.x * blockDim.x + threadIdx.x) * 8;  // n = 16.78M, grid covers exactly
    float4 v0 = *(const float4*)(x + i0);
    float4 v1 = *(const float4*)(x + i0 + 4);
    __half2 h0 = __floats2half2_rn(v0.x, v0.y);
    __half2 h1 = __floats2half2_rn(v0.z, v0.w);
    __half2 h2 = __floats2half2_rn(v1.x, v1.y);
    __half2 h3 = __floats2half2_rn(v1.z, v1.w);
    uint4 u;
    u.x = *(uint32_t*)&h0; u.y = *(uint32_t*)&h1;
    u.z = *(uint32_t*)&h2; u.w = *(uint32_t*)&h3;
    *(uint4*)(g_Xh + i0) = u;
}

// Tiled transpose: W1[e][k][n] (k:ND, n:NF) -> W1T[e][n][k]
__global__ void prep_w1(const float* __restrict__ W1) {
    __shared__ float t[32][33];
    int nt = blockIdx.x, kt = blockIdx.y, e = blockIdx.z;
    int k0 = kt * 32, n0 = nt * 32;
    int r = threadIdx.x >> 5, c = threadIdx.x & 31;
#pragma unroll
    for (int i = 0; i < 4; i++)
        t[r + i * 8][c] = W1[((size_t)e * ND + k0 + r + i * 8) * NF + n0 + c];
    __syncthreads();
#pragma unroll
    for (int i = 0; i < 4; i++)
        g_W1T[((size_t)e * NF + n0 + r + i * 8) * ND + k0 + c] = __float2half(t[c][r + i * 8]);
}

// Tiled transpose: W2[e][k][n] (k:NF, n:ND) -> W2T[e][n][k]
__global__ void prep_w2(const float* __restrict__ W2) {
    __shared__ float t[32][33];
    int nt = blockIdx.x, kt = blockIdx.y, e = blockIdx.z;
    int k0 = kt * 32, n0 = nt * 32;
    int r = threadIdx.x >> 5, c = threadIdx.x & 31;
#pragma unroll
    for (int i = 0; i < 4; i++)
        t[r + i * 8][c] = W2[((size_t)e * NF + k0 + r + i * 8) * ND + n0 + c];
    __syncthreads();
#pragma unroll
    for (int i = 0; i < 4; i++)
        g_W2T[((size_t)e * ND + n0 + r + i * 8) * NF + k0 + c] = __float2half(t[c][r + i * 8]);
}

// ---------------------------------------------------------------------------
// GEMM1: one CTA per active (b, e). X resident in SMEM; W1 B-tiles streamed
// (2-stage, 18KB/chunk). For nt in 0..3: K=256 loop, epilogue
// H = gate*gelu(D + b1) -> fp16, SMEM-staged coalesced stores.
// ---------------------------------------------------------------------------
__global__ void __launch_bounds__(256, 2) gemm1_kernel(const float* __restrict__ b1) {
    const int b = blockIdx.x, e = blockIdx.y;
    const float gate = g_gates[b * NE + e];
    if (gate == 0.0f) return;

    extern __shared__ __align__(128) char sm[];
    const uint32_t smb = smem_u32(sm);
    const int tid = threadIdx.x, lane = tid & 31, wid = tid >> 5;
    const int wm = wid & 1, wn = wid >> 1;

    // Load X[b] (128 x 256 f16) into resident SMEM, overlapped with B prefills.
    {
        const __half* Xs = g_Xh + (size_t)b * NL * ND;
#pragma unroll
        for (int i = 0; i < 16; i++) {
            int q = tid + i * 256;          // 128 rows x 32 16B-chunks
            int r = q >> 5;
            int c = (q & 31) << 3;          // elem col
            cp16(smb + G1_X + r * X_STRIDE + c * 2, Xs + (size_t)r * ND + c);
        }
        CP_COMMIT();
    }

    const __half* Bbase = g_W1T + (size_t)e * NF * ND;

    for (int nt = 0; nt < 4; nt++) {
        const __half* Bt = Bbase + (size_t)(nt * 128) * ND;
        fill_tile(G1_B(0) + smb, Bt, ND, tid); CP_COMMIT();
        fill_tile(G1_B(1) + smb, Bt + 64, ND, tid); CP_COMMIT();

        float acc[4][4][4] = {};
#pragma unroll
        for (int kc = 0; kc < 4; kc++) {
            if (kc < 3) { CP_WAIT1(); } else { CP_WAIT0(); }
            __syncthreads();
            compute_xres(smb, smb + G1_B(kc & 1), kc, wm, wn, lane, acc);
            __syncthreads();
            if (kc + 2 < 4) {
                fill_tile(G1_B(kc & 1) + smb, Bt + (kc + 2) * 64, ND, tid);
                CP_COMMIT();
            }
        }

        // Epilogue: stage gated-GELU fp16 tile (stride 272B) in B area, then
        // coalesced 16B global writes.
        const uint32_t sh = smb + G1_B(0);
        const int r0 = lane >> 2, c0 = (lane & 3) * 2;
#pragma unroll
        for (int mi = 0; mi < 4; mi++) {
#pragma unroll
            for (int ni = 0; ni < 4; ni++) {
                int lc = wn * 32 + ni * 8 + c0;
                float bb0 = __ldg(b1 + e * NF + nt * 128 + lc);
                float bb1 = __ldg(b1 + e * NF + nt * 128 + lc + 1);
#pragma unroll
                for (int h = 0; h < 2; h++) {
                    int row = wm * 64 + mi * 16 + r0 + h * 8;
                    float v0 = gate * gelu_exact(acc[mi][ni][h * 2 + 0] + bb0);
                    float v1 = gate * gelu_exact(acc[mi][ni][h * 2 + 1] + bb1);
                    __half h0 = __float2half(v0);
                    __half h1 = __float2half(v1);
                    uint32_t hp = (uint32_t)__half_as_ushort(h0) |
                                  ((uint32_t)__half_as_ushort(h1) << 16);
                    asm volatile("st.shared.b32 [%0], %1;"
                                 :: "r"(sh + row * 272 + lc * 2), "r"(hp));
                }
            }
        }
        __syncthreads();

        __half* Hp = g_H + (size_t)(b * NE + e) * NL * NF + nt * 128;
#pragma unroll
        for (int it = 0; it < 8; it++) {
            int idx = tid + it * 256;       // 128 rows x 16 16B-units
            int row = idx >> 4;
            int u = idx & 15;
            float4 vh;
            asm volatile("ld.shared.v4.b32 {%0,%1,%2,%3}, [%4];"
                         : "=f"(vh.x), "=f"(vh.y), "=f"(vh.z), "=f"(vh.w)
                         : "r"(sh + row * 272 + u * 16));
            *(float4*)(Hp + (size_t)row * NF + u * 8) = vh;
        }
        __syncthreads();   // staging buffer reused by next nt's fills
    }
}

// ---------------------------------------------------------------------------
// GEMM2: per (b, nt): out = sum_{e active} H_e[128,512] @ W2T_e[.,512]^T
//        + sum_e g_e * b2_e.  3-stage both-stream pipeline.
// ---------------------------------------------------------------------------
__global__ void __launch_bounds__(256, 2) gemm2_kernel(const float* __restrict__ b2,
                                                       float* __restrict__ out) {
    const int b = blockIdx.x, nt = blockIdx.y;
    const int tid = threadIdx.x, lane = tid & 31, wid = tid >> 5;
    const int wm = wid & 1, wn = wid >> 1;
    const int n0 = nt * 128;

    float gates[NE];
    int act[NE], na = 0;
#pragma unroll
    for (int e = 0; e < NE; e++) {
        gates[e] = g_gates[b * NE + e];
        if (gates[e] != 0.0f) act[na++] = e;
    }
    if (na == 0) {
        float4 z = make_float4(0.f, 0.f, 0.f, 0.f);
        float* o = out + (size_t)b * NL * ND + n0;
        for (int i = tid; i < NL * 32; i += 256) {
            int r = i >> 5, c = (i & 31) << 2;
            *(float4*)(o + (size_t)r * ND + c) = z;
        }
        return;
    }

    extern __shared__ __align__(128) char sm[];
    __shared__ float cb[128];
    const uint32_t smb = smem_u32(sm);

    if (tid < 128) {
        float s = 0.f;
#pragma unroll
        for (int e = 0; e < NE; e++) s += gates[e] * __ldg(b2 + e * ND + n0 + tid);
        cb[tid] = s;
    }

    float acc[4][4][4] = {};
    const int total = na * 8;  // per expert: 8 BK=64 chunks over K=512

    auto srcs = [&](int i, const __half*& As, const __half*& Bs) {
        int e = act[i >> 3];
        int k = (i & 7) << 6;
        As = g_H + (size_t)(b * NE + e) * NL * NF + k;
        Bs = g_W2T + ((size_t)e * ND + n0) * NF + k;
    };

    {
        const __half *As, *Bs;
        srcs(0, As, Bs);
        fill_tile(smb + SM_A(0), As, NF, tid);
        fill_tile(smb + SM_B(0), Bs, NF, tid);
        CP_COMMIT();
        srcs(1, As, Bs);
        fill_tile(smb + SM_A(1), As, NF, tid);
        fill_tile(smb + SM_B(1), Bs, NF, tid);
        CP_COMMIT();
    }
    for (int i = 0; i < total; i++) {
        if (i + 1 < total) { CP_WAIT1(); } else { CP_WAIT0(); }
        __syncthreads();
        if (i + 2 < total) {
            const __half *As, *Bs;
            srcs(i + 2, As, Bs);
            fill_tile(smb + SM_A((i + 2) % 3), As, NF, tid);
            fill_tile(smb + SM_B((i + 2) % 3), Bs, NF, tid);
            CP_COMMIT();
        }
        compute_stage(smb, i % 3, wm, wn, lane, acc);
        __syncthreads();
    }

    // Epilogue: add gate-weighted bias, write fp32 out
    const int r0 = lane >> 2, c0 = (lane & 3) * 2;
#pragma unroll
    for (int mi = 0; mi < 4; mi++) {
#pragma unroll
        for (int ni = 0; ni < 4; ni++) {
            int lc = wn * 32 + ni * 8 + c0;
            float bb0 = cb[lc], bb1 = cb[lc + 1];
#pragma unroll
            for (int h = 0; h < 2; h++) {
                int row = wm * 64 + mi * 16 + r0 + h * 8;
                float* o = out + ((size_t)b * NL + row) * ND + n0 + lc;
                float2 v = make_float2(acc[mi][ni][h * 2 + 0] + bb0,
                                       acc[mi][ni][h * 2 + 1] + bb1);
                *(float2*)o = v;
            }
        }
    }
}

// ---------------------------------------------------------------------------
extern "C" void kernel_launch(void* const* d_in, const int* in_sizes, int n_in,
                              void* d_out, int out_size) {
    const float* x      = (const float*)d_in[0];
    const float* logits = (const float*)d_in[1];
    const float* W1     = (const float*)d_in[2];
    const float* b1     = (const float*)d_in[3];
    const float* W2     = (const float*)d_in[4];
    const float* b2     = (const float*)d_in[5];
    const int*   masks  = (const int*)d_in[6];
    float* out = (float*)d_out;

    cudaFuncSetAttribute(gemm1_kernel, cudaFuncAttributeMaxDynamicSharedMemorySize, G1_SMEM);
    cudaFuncSetAttribute(gemm2_kernel, cudaFuncAttributeMaxDynamicSharedMemorySize, G2_SMEM);

    gate_kernel<<<2, 256>>>(logits, masks);
    prep_x<<<(NB * NL * ND) / (256 * 8), 256>>>(x);
    prep_w1<<<dim3(NF / 32, ND / 32, NE), 256>>>(W1);
    prep_w2<<<dim3(ND / 32, NF / 32, NE), 256>>>(W2);
    gemm1_kernel<<<dim3(NB, NE), 256, G1_SMEM>>>(b1);
    gemm2_kernel<<<dim3(NB, ND / 128), 256, G2_SMEM>>>(b2, out);
}

// round 9
// speedup vs baseline: 6.7165x; 1.0125x over previous
#include <cuda_runtime.h>
#include <cuda_fp16.h>
#include <math.h>
#include <stdint.h>

#define NB 512
#define NL 128
#define ND 256
#define NF 512
#define NE 8

// ---------------------------------------------------------------------------
// Device scratch (allocation-free rule)
// ---------------------------------------------------------------------------
__device__ float g_gates[NB * NE];
__device__ __half g_Xh[(size_t)NB * NL * ND];
__device__ __half g_W1T[(size_t)NE * NF * ND];   // [e][n][k]
__device__ __half g_W2T[(size_t)NE * ND * NF];   // [e][n][k]
__device__ __half g_H[(size_t)NB * NE * NL * NF];

// ---------------------------------------------------------------------------
// PTX helpers — baseline (non-'a') features only: cp.async, ldmatrix, mma.sync
// ---------------------------------------------------------------------------
__device__ __forceinline__ uint32_t smem_u32(const void* p) {
    uint32_t a;
    asm("{ .reg .u64 t; cvta.to.shared.u64 t, %1; cvt.u32.u64 %0, t; }" : "=r"(a) : "l"(p));
    return a;
}
__device__ __forceinline__ void cp16(uint32_t dst, const void* src) {
    asm volatile("cp.async.cg.shared.global [%0], [%1], 16;" :: "r"(dst), "l"(src));
}
#define CP_COMMIT() asm volatile("cp.async.commit_group;" ::: "memory")
#define CP_WAIT0()  asm volatile("cp.async.wait_group 0;" ::: "memory")
#define CP_WAIT1()  asm volatile("cp.async.wait_group 1;" ::: "memory")

#define LDSM4(r0, r1, r2, r3, addr) \
    asm volatile("ldmatrix.sync.aligned.m8n8.x4.shared.b16 {%0,%1,%2,%3}, [%4];" \
                 : "=r"(r0), "=r"(r1), "=r"(r2), "=r"(r3) : "r"(addr))

#define MMA16816(c, a, b0, b1) \
    asm volatile("mma.sync.aligned.m16n8k16.row.col.f32.f16.f16.f32 " \
                 "{%0,%1,%2,%3}, {%4,%5,%6,%7}, {%8,%9}, {%0,%1,%2,%3};" \
                 : "+f"((c)[0]), "+f"((c)[1]), "+f"((c)[2]), "+f"((c)[3]) \
                 : "r"((a)[0]), "r"((a)[1]), "r"((a)[2]), "r"((a)[3]), \
                   "r"(b0), "r"(b1))

__device__ __forceinline__ float gelu_exact(float v) {
    return 0.5f * v * (1.0f + erff(v * 0.70710678118654752f));
}

// ---------------------------------------------------------------------------
// Tile geometry
// ---------------------------------------------------------------------------
#define ROW_BYTES 144                               // streamed 64-col tiles
#define TILE_BYTES (128 * ROW_BYTES)                // 18432
// GEMM1 SMEM: X resident [128][264] f16 (stride 528B) + 2 B stages
#define X_STRIDE 528
#define G1_X 0
#define G1_B(st) (67584 + (st) * TILE_BYTES)
#define G1_SMEM (67584 + 2 * TILE_BYTES)            // 104448
// GEMM2 SMEM: 3 stages x (A+B)
#define STAGE_BYTES (2 * TILE_BYTES)                // 36864
#define SM_A(st) ((st) * STAGE_BYTES)
#define SM_B(st) ((st) * STAGE_BYTES + TILE_BYTES)
#define G2_SMEM (3 * STAGE_BYTES)                   // 110592

// Fill a [128 x 64] f16 tile (stride ROW_BYTES) via cp.async: 4 x 16B/thread.
__device__ __forceinline__ void fill_tile(uint32_t dst, const __half* src,
                                          int stride, int tid) {
#pragma unroll
    for (int i = 0; i < 4; i++) {
        int q = tid + i * 256;
        int r = q >> 3;
        int c = (q & 7) << 3;
        cp16(dst + r * ROW_BYTES + c * 2, src + (size_t)r * stride + c);
    }
}

// GEMM2-style compute: A and B both in streamed tiles.
__device__ __forceinline__ void compute_stage(uint32_t smb, int st, int wm, int wn,
                                              int lane, float acc[4][4][4]) {
#pragma unroll
    for (int ks = 0; ks < 4; ks++) {
        uint32_t a[4][4];
#pragma unroll
        for (int mi = 0; mi < 4; mi++) {
            uint32_t ad = smb + SM_A(st) +
                (wm * 64 + mi * 16 + (lane & 15)) * ROW_BYTES + ks * 32 + (lane >> 4) * 16;
            LDSM4(a[mi][0], a[mi][1], a[mi][2], a[mi][3], ad);
        }
        uint32_t bfr[2][4];
        int quad = lane >> 3;
#pragma unroll
        for (int g = 0; g < 2; g++) {
            uint32_t bd = smb + SM_B(st) +
                (wn * 32 + g * 16 + (quad >> 1) * 8 + (lane & 7)) * ROW_BYTES +
                ks * 32 + (quad & 1) * 16;
            LDSM4(bfr[g][0], bfr[g][1], bfr[g][2], bfr[g][3], bd);
        }
#pragma unroll
        for (int mi = 0; mi < 4; mi++)
#pragma unroll
            for (int ni = 0; ni < 4; ni++)
                MMA16816(acc[mi][ni], a[mi],
                         bfr[ni >> 1][(ni & 1) * 2], bfr[ni >> 1][(ni & 1) * 2 + 1]);
    }
}

// GEMM1 compute: A from resident X (stride 528B, chunk kc), B from streamed tile.
__device__ __forceinline__ void compute_xres(uint32_t smb, uint32_t bst, int kc,
                                             int wm, int wn, int lane,
                                             float acc[4][4][4]) {
#pragma unroll
    for (int ks = 0; ks < 4; ks++) {
        uint32_t a[4][4];
#pragma unroll
        for (int mi = 0; mi < 4; mi++) {
            uint32_t ad = smb + G1_X +
                (wm * 64 + mi * 16 + (lane & 15)) * X_STRIDE + kc * 128 + ks * 32 +
                (lane >> 4) * 16;
            LDSM4(a[mi][0], a[mi][1], a[mi][2], a[mi][3], ad);
        }
        uint32_t bfr[2][4];
        int quad = lane >> 3;
#pragma unroll
        for (int g = 0; g < 2; g++) {
            uint32_t bd = bst +
                (wn * 32 + g * 16 + (quad >> 1) * 8 + (lane & 7)) * ROW_BYTES +
                ks * 32 + (quad & 1) * 16;
            LDSM4(bfr[g][0], bfr[g][1], bfr[g][2], bfr[g][3], bd);
        }
#pragma unroll
        for (int mi = 0; mi < 4; mi++)
#pragma unroll
            for (int ni = 0; ni < 4; ni++)
                MMA16816(acc[mi][ni], a[mi],
                         bfr[ni >> 1][(ni & 1) * 2], bfr[ni >> 1][(ni & 1) * 2 + 1]);
    }
}

// ---------------------------------------------------------------------------
// Merged prep kernel: one launch covers gates + X convert + W1/W2 transposes.
// Grid layout: [0, 8192)            prep_x (8 f32->f16 per thread)
//              [8192, 9216)         prep_w1 tiles (16 x 8 x 8)
//              [9216, 10240)        prep_w2 tiles (8 x 16 x 8)
//              [10240, 10242)       gates
// ---------------------------------------------------------------------------
#define PREP_GRID 10242

__global__ void prep_kernel(const float* __restrict__ x,
                            const float* __restrict__ W1,
                            const float* __restrict__ W2,
                            const float* __restrict__ logits,
                            const int* __restrict__ masks) {
    __shared__ float t[32][33];
    const int bid = blockIdx.x;
    if (bid < 8192) {
        size_t i0 = ((size_t)bid * 256 + threadIdx.x) * 8;
        float4 v0 = *(const float4*)(x + i0);
        float4 v1 = *(const float4*)(x + i0 + 4);
        __half2 h0 = __floats2half2_rn(v0.x, v0.y);
        __half2 h1 = __floats2half2_rn(v0.z, v0.w);
        __half2 h2 = __floats2half2_rn(v1.x, v1.y);
        __half2 h3 = __floats2half2_rn(v1.z, v1.w);
        uint4 u;
        u.x = *(uint32_t*)&h0; u.y = *(uint32_t*)&h1;
        u.z = *(uint32_t*)&h2; u.w = *(uint32_t*)&h3;
        *(uint4*)(g_Xh + i0) = u;
    } else if (bid < 9216) {
        int id = bid - 8192;                 // nt(16) x kt(8) x e(8)
        int nt = id & 15, kt = (id >> 4) & 7, e = id >> 7;
        int k0 = kt * 32, n0 = nt * 32;
        int r = threadIdx.x >> 5, c = threadIdx.x & 31;
#pragma unroll
        for (int i = 0; i < 4; i++)
            t[r + i * 8][c] = W1[((size_t)e * ND + k0 + r + i * 8) * NF + n0 + c];
        __syncthreads();
#pragma unroll
        for (int i = 0; i < 4; i++)
            g_W1T[((size_t)e * NF + n0 + r + i * 8) * ND + k0 + c] =
                __float2half(t[c][r + i * 8]);
    } else if (bid < 10240) {
        int id = bid - 9216;                 // nt(8) x kt(16) x e(8)
        int nt = id & 7, kt = (id >> 3) & 15, e = id >> 7;
        int k0 = kt * 32, n0 = nt * 32;
        int r = threadIdx.x >> 5, c = threadIdx.x & 31;
#pragma unroll
        for (int i = 0; i < 4; i++)
            t[r + i * 8][c] = W2[((size_t)e * NF + k0 + r + i * 8) * ND + n0 + c];
        __syncthreads();
#pragma unroll
        for (int i = 0; i < 4; i++)
            g_W2T[((size_t)e * ND + n0 + r + i * 8) * NF + k0 + c] =
                __float2half(t[c][r + i * 8]);
    } else {
        int b = (bid - 10240) * 256 + threadIdx.x;
        if (b >= NB) return;
        float v[NE]; float mx = -1e30f;
#pragma unroll
        for (int e = 0; e < NE; e++) { v[e] = logits[b * NE + e]; mx = fmaxf(mx, v[e]); }
        float s = 0.f;
#pragma unroll
        for (int e = 0; e < NE; e++) { v[e] = expf(v[e] - mx); s += v[e]; }
        float inv = 1.f / s; float gs = 0.f;
#pragma unroll
        for (int e = 0; e < NE; e++) {
            v[e] = (masks[b * NE + e] == 1) ? v[e] * inv : 0.f;
            gs += v[e];
        }
        float d = 1.f / (gs + 1e-9f);
#pragma unroll
        for (int e = 0; e < NE; e++) g_gates[b * NE + e] = v[e] * d;
    }
}

// ---------------------------------------------------------------------------
// GEMM1: one CTA per active (b, e). X resident in SMEM; W1 B-tiles streamed
// (2-stage, 18KB/chunk). For nt in 0..3: K=256 loop, epilogue
// H = gate*gelu(D + b1) -> fp16, SMEM-staged coalesced stores.
// ---------------------------------------------------------------------------
__global__ void __launch_bounds__(256, 2) gemm1_kernel(const float* __restrict__ b1) {
    const int b = blockIdx.x, e = blockIdx.y;
    const float gate = g_gates[b * NE + e];
    if (gate == 0.0f) return;

    extern __shared__ __align__(128) char sm[];
    const uint32_t smb = smem_u32(sm);
    const int tid = threadIdx.x, lane = tid & 31, wid = tid >> 5;
    const int wm = wid & 1, wn = wid >> 1;

    // Load X[b] (128 x 256 f16) into resident SMEM.
    {
        const __half* Xs = g_Xh + (size_t)b * NL * ND;
#pragma unroll
        for (int i = 0; i < 16; i++) {
            int q = tid + i * 256;          // 128 rows x 32 16B-chunks
            int r = q >> 5;
            int c = (q & 31) << 3;
            cp16(smb + G1_X + r * X_STRIDE + c * 2, Xs + (size_t)r * ND + c);
        }
        CP_COMMIT();
    }

    const __half* Bbase = g_W1T + (size_t)e * NF * ND;

    for (int nt = 0; nt < 4; nt++) {
        const __half* Bt = Bbase + (size_t)(nt * 128) * ND;
        fill_tile(G1_B(0) + smb, Bt, ND, tid); CP_COMMIT();
        fill_tile(G1_B(1) + smb, Bt + 64, ND, tid); CP_COMMIT();

        float acc[4][4][4] = {};
#pragma unroll
        for (int kc = 0; kc < 4; kc++) {
            if (kc < 3) { CP_WAIT1(); } else { CP_WAIT0(); }
            __syncthreads();
            compute_xres(smb, smb + G1_B(kc & 1), kc, wm, wn, lane, acc);
            __syncthreads();
            if (kc + 2 < 4) {
                fill_tile(G1_B(kc & 1) + smb, Bt + (kc + 2) * 64, ND, tid);
                CP_COMMIT();
            }
        }

        // Epilogue: stage gated-GELU fp16 tile (stride 272B) in B area, then
        // coalesced 16B global writes.
        const uint32_t sh = smb + G1_B(0);
        const int r0 = lane >> 2, c0 = (lane & 3) * 2;
#pragma unroll
        for (int mi = 0; mi < 4; mi++) {
#pragma unroll
            for (int ni = 0; ni < 4; ni++) {
                int lc = wn * 32 + ni * 8 + c0;
                float bb0 = __ldg(b1 + e * NF + nt * 128 + lc);
                float bb1 = __ldg(b1 + e * NF + nt * 128 + lc + 1);
#pragma unroll
                for (int h = 0; h < 2; h++) {
                    int row = wm * 64 + mi * 16 + r0 + h * 8;
                    float v0 = gate * gelu_exact(acc[mi][ni][h * 2 + 0] + bb0);
                    float v1 = gate * gelu_exact(acc[mi][ni][h * 2 + 1] + bb1);
                    __half h0 = __float2half(v0);
                    __half h1 = __float2half(v1);
                    uint32_t hp = (uint32_t)__half_as_ushort(h0) |
                                  ((uint32_t)__half_as_ushort(h1) << 16);
                    asm volatile("st.shared.b32 [%0], %1;"
                                 :: "r"(sh + row * 272 + lc * 2), "r"(hp));
                }
            }
        }
        __syncthreads();

        __half* Hp = g_H + (size_t)(b * NE + e) * NL * NF + nt * 128;
#pragma unroll
        for (int it = 0; it < 8; it++) {
            int idx = tid + it * 256;       // 128 rows x 16 16B-units
            int row = idx >> 4;
            int u = idx & 15;
            float4 vh;
            asm volatile("ld.shared.v4.b32 {%0,%1,%2,%3}, [%4];"
                         : "=f"(vh.x), "=f"(vh.y), "=f"(vh.z), "=f"(vh.w)
                         : "r"(sh + row * 272 + u * 16));
            *(float4*)(Hp + (size_t)row * NF + u * 8) = vh;
        }
        __syncthreads();   // staging buffer reused by next nt's fills
    }
}

// ---------------------------------------------------------------------------
// GEMM2: per (b, nt): out = sum_{e active} H_e[128,512] @ W2T_e[.,512]^T
//        + sum_e g_e * b2_e.  3-stage pipeline, ONE barrier per chunk:
// fill((i+2)%3) after the head barrier of chunk i only races readers of
// compute(i-1) (same stage mod 3), and every thread finished compute(i-1)
// before that barrier — WAR ordered by the head barrier alone.
// ---------------------------------------------------------------------------
__global__ void __launch_bounds__(256, 2) gemm2_kernel(const float* __restrict__ b2,
                                                       float* __restrict__ out) {
    const int b = blockIdx.x, nt = blockIdx.y;
    const int tid = threadIdx.x, lane = tid & 31, wid = tid >> 5;
    const int wm = wid & 1, wn = wid >> 1;
    const int n0 = nt * 128;

    float gates[NE];
    int act[NE], na = 0;
#pragma unroll
    for (int e = 0; e < NE; e++) {
        gates[e] = g_gates[b * NE + e];
        if (gates[e] != 0.0f) act[na++] = e;
    }
    if (na == 0) {
        float4 z = make_float4(0.f, 0.f, 0.f, 0.f);
        float* o = out + (size_t)b * NL * ND + n0;
        for (int i = tid; i < NL * 32; i += 256) {
            int r = i >> 5, c = (i & 31) << 2;
            *(float4*)(o + (size_t)r * ND + c) = z;
        }
        return;
    }

    extern __shared__ __align__(128) char sm[];
    __shared__ float cb[128];
    const uint32_t smb = smem_u32(sm);

    if (tid < 128) {
        float s = 0.f;
#pragma unroll
        for (int e = 0; e < NE; e++) s += gates[e] * __ldg(b2 + e * ND + n0 + tid);
        cb[tid] = s;
    }

    float acc[4][4][4] = {};
    const int total = na * 8;  // per expert: 8 BK=64 chunks over K=512

    auto srcs = [&](int i, const __half*& As, const __half*& Bs) {
        int e = act[i >> 3];
        int k = (i & 7) << 6;
        As = g_H + (size_t)(b * NE + e) * NL * NF + k;
        Bs = g_W2T + ((size_t)e * ND + n0) * NF + k;
    };

    {
        const __half *As, *Bs;
        srcs(0, As, Bs);
        fill_tile(smb + SM_A(0), As, NF, tid);
        fill_tile(smb + SM_B(0), Bs, NF, tid);
        CP_COMMIT();
        srcs(1, As, Bs);
        fill_tile(smb + SM_A(1), As, NF, tid);
        fill_tile(smb + SM_B(1), Bs, NF, tid);
        CP_COMMIT();
    }
    for (int i = 0; i < total; i++) {
        if (i + 1 < total) { CP_WAIT1(); } else { CP_WAIT0(); }
        __syncthreads();                     // single barrier per chunk
        if (i + 2 < total) {
            const __half *As, *Bs;
            srcs(i + 2, As, Bs);
            fill_tile(smb + SM_A((i + 2) % 3), As, NF, tid);
            fill_tile(smb + SM_B((i + 2) % 3), Bs, NF, tid);
            CP_COMMIT();
        }
        compute_stage(smb, i % 3, wm, wn, lane, acc);
    }

    // Epilogue: add gate-weighted bias, write fp32 out
    const int r0 = lane >> 2, c0 = (lane & 3) * 2;
#pragma unroll
    for (int mi = 0; mi < 4; mi++) {
#pragma unroll
        for (int ni = 0; ni < 4; ni++) {
            int lc = wn * 32 + ni * 8 + c0;
            float bb0 = cb[lc], bb1 = cb[lc + 1];
#pragma unroll
            for (int h = 0; h < 2; h++) {
                int row = wm * 64 + mi * 16 + r0 + h * 8;
                float* o = out + ((size_t)b * NL + row) * ND + n0 + lc;
                float2 v = make_float2(acc[mi][ni][h * 2 + 0] + bb0,
                                       acc[mi][ni][h * 2 + 1] + bb1);
                *(float2*)o = v;
            }
        }
    }
}

// ---------------------------------------------------------------------------
extern "C" void kernel_launch(void* const* d_in, const int* in_sizes, int n_in,
                              void* d_out, int out_size) {
    const float* x      = (const float*)d_in[0];
    const float* logits = (const float*)d_in[1];
    const float* W1     = (const float*)d_in[2];
    const float* b1     = (const float*)d_in[3];
    const float* W2     = (const float*)d_in[4];
    const float* b2     = (const float*)d_in[5];
    const int*   masks  = (const int*)d_in[6];
    float* out = (float*)d_out;

    cudaFuncSetAttribute(gemm1_kernel, cudaFuncAttributeMaxDynamicSharedMemorySize, G1_SMEM);
    cudaFuncSetAttribute(gemm2_kernel, cudaFuncAttributeMaxDynamicSharedMemorySize, G2_SMEM);

    prep_kernel<<<PREP_GRID, 256>>>(x, W1, W2, logits, masks);
    gemm1_kernel<<<dim3(NB, NE), 256, G1_SMEM>>>(b1);
    gemm2_kernel<<<dim3(NB, ND / 128), 256, G2_SMEM>>>(b2, out);
}